// round 12
// baseline (speedup 1.0000x reference)
#include <cuda_runtime.h>
#include <cuda_bf16.h>
#include <cuda_fp16.h>
#include <cstdint>

#define N_NODES 100000
#define N_FEAT  512
#define HIDDEN  128
#define N_CLASS 16
#define N_EDGES 3200000
#define ALPHA   0.25f

#define NCHUNK 98   // ceil(100000/1024)

// ---------------- device scratch ----------------
__device__ float  g_local[N_NODES * N_CLASS];      // fp32 local logits (self term)
__device__ __half g_localh[N_NODES * N_CLASS];     // fp16 gather table, iter 1
__device__ __half g_tmph[N_NODES * N_CLASS];       // fp16 gather table, iter 2
__device__ int    g_cnt[N_NODES];
__device__ int    g_rowptr[N_NODES + 1];
__device__ int    g_fill[N_NODES];
__device__ float  g_scale[N_NODES];
__device__ int    g_csr[N_EDGES];
__device__ int    g_chunksum[NCHUNK];
__device__ uint32_t g_W1h[(N_FEAT / 2) * HIDDEN];  // W1 packed as half2 over k-pairs

// ---------------- helpers ----------------
__device__ __forceinline__ uint32_t packh(float a, float b) {
    __half2 t = __floats2half2_rn(a, b);
    return *(uint32_t*)&t;
}

__device__ __forceinline__ void mma_f16(float* d, const uint32_t* a,
                                        uint32_t b0, uint32_t b1) {
    asm volatile(
        "mma.sync.aligned.m16n8k16.row.col.f32.f16.f16.f32 "
        "{%0,%1,%2,%3},{%4,%5,%6,%7},{%8,%9},{%0,%1,%2,%3};\n"
        : "+f"(d[0]), "+f"(d[1]), "+f"(d[2]), "+f"(d[3])
        : "r"(a[0]), "r"(a[1]), "r"(a[2]), "r"(a[3]), "r"(b0), "r"(b1));
}

__device__ __forceinline__ void cp16(uint32_t dst, const void* src) {
    asm volatile("cp.async.cg.shared.global [%0], [%1], 16;\n"
                 :: "r"(dst), "l"(src) : "memory");
}
#define CP_COMMIT asm volatile("cp.async.commit_group;\n" ::: "memory")
#define CP_WAIT(N) asm volatile("cp.async.wait_group %0;\n" :: "n"(N) : "memory")

// ---------------- W1 pre-conversion: pack (k, k+1) pairs into half2 ----------------
__global__ void k_cvt_w1(const float* __restrict__ W1) {
    int i = blockIdx.x * blockDim.x + threadIdx.x;
    if (i < (N_FEAT / 2) * HIDDEN) {
        int kk = i / HIDDEN;      // k-pair index
        int n  = i % HIDDEN;
        g_W1h[i] = packh(W1[(2 * kk) * HIDDEN + n], W1[(2 * kk + 1) * HIDDEN + n]);
    }
}

// ---------------- CSR build ----------------
__global__ void k_zero_cnt() {
    int i = blockIdx.x * blockDim.x + threadIdx.x;
    if (i < N_NODES) g_cnt[i] = 0;
    if (i == 0) g_rowptr[N_NODES] = N_EDGES;
}

__global__ void k_hist(const int* __restrict__ esrc) {
    int t = blockIdx.x * blockDim.x + threadIdx.x;
    if (t < N_EDGES / 4) {
        int4 s = ((const int4*)esrc)[t];
        atomicAdd(&g_cnt[s.x], 1);
        atomicAdd(&g_cnt[s.y], 1);
        atomicAdd(&g_cnt[s.z], 1);
        atomicAdd(&g_cnt[s.w], 1);
    }
}

// scan phase 1: per-1024-chunk sums
__global__ void k_scan1() {
    __shared__ int ws[32];
    int tid = threadIdx.x, lane = tid & 31, wid = tid >> 5;
    int i = blockIdx.x * 1024 + tid;
    int v = (i < N_NODES) ? g_cnt[i] : 0;
    #pragma unroll
    for (int d = 16; d >= 1; d >>= 1) v += __shfl_xor_sync(0xffffffffu, v, d);
    if (lane == 0) ws[wid] = v;
    __syncthreads();
    if (wid == 0) {
        int s = ws[lane];
        #pragma unroll
        for (int d = 16; d >= 1; d >>= 1) s += __shfl_xor_sync(0xffffffffu, s, d);
        if (lane == 0) g_chunksum[blockIdx.x] = s;
    }
}

// scan phase 3: chunk-prefix (folded) + in-chunk exclusive scan
__global__ void k_scan3() {
    __shared__ int ws[32];
    __shared__ int s_pre[4];
    int tid = threadIdx.x, lane = tid & 31, wid = tid >> 5;

    if (tid < 128) {
        int vp = (tid < blockIdx.x) ? g_chunksum[tid] : 0;
        #pragma unroll
        for (int d = 16; d >= 1; d >>= 1) vp += __shfl_xor_sync(0xffffffffu, vp, d);
        if (lane == 0) s_pre[wid] = vp;
    }

    int i = blockIdx.x * 1024 + tid;
    int v = (i < N_NODES) ? g_cnt[i] : 0;
    int x = v;
    #pragma unroll
    for (int d = 1; d < 32; d <<= 1) {
        int y = __shfl_up_sync(0xffffffffu, x, d);
        if (lane >= d) x += y;
    }
    if (lane == 31) ws[wid] = x;
    __syncthreads();
    if (wid == 0) {
        int w = ws[lane];
        int xs = w;
        #pragma unroll
        for (int d = 1; d < 32; d <<= 1) {
            int y = __shfl_up_sync(0xffffffffu, xs, d);
            if (lane >= d) xs += y;
        }
        ws[lane] = xs;
    }
    __syncthreads();
    int coff = s_pre[0] + s_pre[1] + s_pre[2] + s_pre[3];
    int warp_prefix = (wid > 0) ? ws[wid - 1] : 0;
    int excl = x - v + warp_prefix + coff;
    if (i < N_NODES) {
        g_rowptr[i] = excl;
        g_fill[i]   = excl;
        g_scale[i]  = (1.0f - ALPHA) / fmaxf((float)v, 1e-12f);
    }
}

__global__ void k_scatter(const int* __restrict__ esrc, const int* __restrict__ edst) {
    int t = blockIdx.x * blockDim.x + threadIdx.x;
    if (t < N_EDGES / 4) {
        int4 s = ((const int4*)esrc)[t];
        int4 d = ((const int4*)edst)[t];
        int p;
        p = atomicAdd(&g_fill[s.x], 1); g_csr[p] = d.x;
        p = atomicAdd(&g_fill[s.y], 1); g_csr[p] = d.y;
        p = atomicAdd(&g_fill[s.z], 1); g_csr[p] = d.z;
        p = atomicAdd(&g_fill[s.w], 1); g_csr[p] = d.w;
    }
}

// ---------------- fused GEMM: local = relu(x@W1) @ W2, fp16 MMA ----------------
// BM=64, BN=128, BK=32, 256 thr = 8 warps (2m x 4n), warp tile 32x32 (acc=32
// regs) -> 3 CTAs/SM co-resident (occupancy lever). 3-stage cp.async pipeline.
#define GBM 64
#define GBK 32
#define ASTR 36
#define BSTR 136
#define NSTAGE 3
#define A_BYTES (GBM * ASTR * 4)            // 9216
#define B_BYTES (16 * BSTR * 4)             // 8704 (16 k-pair rows)
#define STAGE_BYTES (A_BYTES + B_BYTES)     // 17920
#define STAGES_BYTES (NSTAGE * STAGE_BYTES) // 53760
#define HIDSTR 129
#define HID_BYTES (GBM * HIDSTR * 4)        // 33024 (overlays stages)
#define W2_OFF STAGES_BYTES                 // 53760
#define OUTS_OFF (W2_OFF + HIDDEN * N_CLASS * 4)  // 61952
#define OUTSTR 17
#define GEMM_SMEM (OUTS_OFF + GBM * OUTSTR * 4)   // 66304
#define NKITER (N_FEAT / GBK)               // 16

__global__ __launch_bounds__(256, 3) void k_gemm(const float* __restrict__ x,
                                                 const float* __restrict__ W2) {
    extern __shared__ __align__(16) char sm[];
    float* W2s  = (float*)(sm + W2_OFF);
    float* outS = (float*)(sm + OUTS_OFF);
    float* hid  = (float*)sm;
    uint32_t smem_u32 = (uint32_t)__cvta_generic_to_shared(sm);

    int tid  = threadIdx.x;
    int lane = tid & 31;
    int warp = tid >> 5;
    int blockRow = blockIdx.x * GBM;

    int warpM = warp >> 2;   // 0..1
    int warpN = warp & 3;    // 0..3
    int grp = lane >> 2;     // 0..7
    int tig = lane & 3;      // 0..3

    for (int i = tid; i < HIDDEN * N_CLASS; i += 256) W2s[i] = W2[i];

    float acc[2][4][4];
    #pragma unroll
    for (int mt = 0; mt < 2; mt++)
        #pragma unroll
        for (int nt = 0; nt < 4; nt++)
            #pragma unroll
            for (int r = 0; r < 4; r++) acc[mt][nt][r] = 0.0f;

    auto load_tiles = [&](int kiter) {
        int st = kiter % NSTAGE;
        int k0 = kiter * GBK;
        uint32_t abase = smem_u32 + st * STAGE_BYTES;
        uint32_t bbase = abase + A_BYTES;
        // A: 64 rows x 8 float4 = 512 loads / 256 threads = 2 each
        #pragma unroll
        for (int it = 0; it < 2; it++) {
            int idx = tid + it * 256;
            int r = idx >> 3, c4 = idx & 7;
            int gr = blockRow + r;
            if (gr >= N_NODES) gr = N_NODES - 1;
            cp16(abase + (r * ASTR + c4 * 4) * 4,
                 &x[(size_t)gr * N_FEAT + k0 + c4 * 4]);
        }
        // B: 16 k-pair rows x 32 float4 = 512 loads / 256 threads = 2 each
        #pragma unroll
        for (int it = 0; it < 2; it++) {
            int idx = tid + it * 256;
            int r = idx >> 5, c4 = idx & 31;
            cp16(bbase + (r * BSTR + c4 * 4) * 4,
                 &g_W1h[(kiter * 16 + r) * HIDDEN + c4 * 4]);
        }
        CP_COMMIT;
    };

    auto compute = [&](int kiter) {
        int st = kiter % NSTAGE;
        const uint32_t* As = (const uint32_t*)(sm + st * STAGE_BYTES);
        const uint32_t* Bs = (const uint32_t*)(sm + st * STAGE_BYTES + A_BYTES);
        #pragma unroll
        for (int ks = 0; ks < 2; ks++) {       // two k16 steps per 32-k tile
            int kb = ks * 16;
            uint32_t a[2][4];
            #pragma unroll
            for (int mt = 0; mt < 2; mt++) {
                int r0 = warpM * 32 + mt * 16 + grp;
                float2 lo0 = *(const float2*)&As[r0 * ASTR + kb + 2 * tig];
                float2 lo1 = *(const float2*)&As[(r0 + 8) * ASTR + kb + 2 * tig];
                float2 hi0 = *(const float2*)&As[r0 * ASTR + kb + 8 + 2 * tig];
                float2 hi1 = *(const float2*)&As[(r0 + 8) * ASTR + kb + 8 + 2 * tig];
                a[mt][0] = packh(lo0.x, lo0.y);
                a[mt][1] = packh(lo1.x, lo1.y);
                a[mt][2] = packh(hi0.x, hi0.y);
                a[mt][3] = packh(hi1.x, hi1.y);
            }
            #pragma unroll
            for (int nt = 0; nt < 4; nt++) {
                int col = warpN * 32 + nt * 8 + grp;
                uint32_t b0 = Bs[(ks * 8 + tig) * BSTR + col];
                uint32_t b1 = Bs[(ks * 8 + 4 + tig) * BSTR + col];
                mma_f16(acc[0][nt], a[0], b0, b1);
                mma_f16(acc[1][nt], a[1], b0, b1);
            }
        }
    };

    // 3-stage pipeline
    load_tiles(0);
    load_tiles(1);
    #pragma unroll 1
    for (int i = 0; i < NKITER; i++) {
        if (i < NKITER - 2) { CP_WAIT(1); } else { CP_WAIT(0); }
        __syncthreads();
        if (i + 2 < NKITER) load_tiles(i + 2);
        compute(i);
    }
    __syncthreads();

    // relu -> hid
    #pragma unroll
    for (int mt = 0; mt < 2; mt++) {
        int r0 = warpM * 32 + mt * 16 + grp;
        #pragma unroll
        for (int nt = 0; nt < 4; nt++) {
            int c = warpN * 32 + nt * 8 + tig * 2;
            hid[r0 * HIDSTR + c]           = fmaxf(acc[mt][nt][0], 0.f);
            hid[r0 * HIDSTR + c + 1]       = fmaxf(acc[mt][nt][1], 0.f);
            hid[(r0 + 8) * HIDSTR + c]     = fmaxf(acc[mt][nt][2], 0.f);
            hid[(r0 + 8) * HIDSTR + c + 1] = fmaxf(acc[mt][nt][3], 0.f);
        }
    }
    __syncthreads();

    // second gemm: out[64][16] = hid[64][128] @ W2[128][16], 4-way h split
    int r = tid & 63;
    int q = tid >> 6;   // 0..3, each handles 32 h-dims
    float o[N_CLASS];
    #pragma unroll
    for (int c = 0; c < N_CLASS; c++) o[c] = 0.f;
    int h0 = q * 32;
    #pragma unroll 4
    for (int h = h0; h < h0 + 32; h++) {
        float v = hid[r * HIDSTR + h];
        #pragma unroll
        for (int c = 0; c < N_CLASS; c++) o[c] += v * W2s[h * N_CLASS + c];
    }
    if (q == 0) {
        #pragma unroll
        for (int c = 0; c < N_CLASS; c++) outS[r * OUTSTR + c] = o[c];
    }
    __syncthreads();
    if (q == 1) {
        #pragma unroll
        for (int c = 0; c < N_CLASS; c++) outS[r * OUTSTR + c] += o[c];
    }
    __syncthreads();
    if (q == 2) {
        #pragma unroll
        for (int c = 0; c < N_CLASS; c++) outS[r * OUTSTR + c] += o[c];
    }
    __syncthreads();
    if (q == 3) {
        int gr = blockRow + r;
        if (gr < N_NODES) {
            float vv[N_CLASS];
            #pragma unroll
            for (int c = 0; c < N_CLASS; c++) vv[c] = outS[r * OUTSTR + c] + o[c];
            #pragma unroll
            for (int j = 0; j < 4; j++) {
                float4 v4 = make_float4(vv[j*4+0], vv[j*4+1], vv[j*4+2], vv[j*4+3]);
                *(float4*)&g_local[gr * N_CLASS + j * 4] = v4;
            }
            uint4 h0v, h1v;
            h0v.x = packh(vv[0],  vv[1]);  h0v.y = packh(vv[2],  vv[3]);
            h0v.z = packh(vv[4],  vv[5]);  h0v.w = packh(vv[6],  vv[7]);
            h1v.x = packh(vv[8],  vv[9]);  h1v.y = packh(vv[10], vv[11]);
            h1v.z = packh(vv[12], vv[13]); h1v.w = packh(vv[14], vv[15]);
            *(uint4*)&g_localh[gr * N_CLASS]     = h0v;
            *(uint4*)&g_localh[gr * N_CLASS + 8] = h1v;
        }
    }
}

// ---------------- SpMM: 16 lanes = 16 classes per node, fp16 gather tables ----------------
template<int PHASE>
__global__ void k_spmm_t(float* __restrict__ outfinal) {
    const __half* tbl = (PHASE == 0) ? g_localh : g_tmph;
    int t = blockIdx.x * blockDim.x + threadIdx.x;
    int node = t >> 4;
    if (node >= N_NODES) return;
    int l16 = threadIdx.x & 15;
    unsigned mask = 0xFFFFu << (threadIdx.x & 16);

    int s = g_rowptr[node], e = g_rowptr[node + 1];
    float a = 0.f;
    int i = s;
    for (; i + 16 <= e; i += 16) {
        int idx = __ldg(&g_csr[i + l16]);
        #pragma unroll
        for (int q = 0; q < 16; q++) {
            int j = __shfl_sync(mask, idx, q, 16);
            a += __half2float(__ldg(&tbl[j * N_CLASS + l16]));
        }
    }
    int rem = e - i;
    if (rem) {
        int idx = (l16 < rem) ? __ldg(&g_csr[i + l16]) : 0;
        for (int q = 0; q < rem; q++) {
            int j = __shfl_sync(mask, idx, q, 16);
            a += __half2float(__ldg(&tbl[j * N_CLASS + l16]));
        }
    }
    float v = g_scale[node] * a + ALPHA * g_local[node * N_CLASS + l16];

    if (PHASE == 0) {
        g_tmph[node * N_CLASS + l16] = __float2half_rn(v);
    } else {
        float m = v;
        #pragma unroll
        for (int k = 8; k >= 1; k >>= 1) m = fmaxf(m, __shfl_xor_sync(mask, m, k, 16));
        float ex = __expf(v - m);
        float ss = ex;
        #pragma unroll
        for (int k = 8; k >= 1; k >>= 1) ss += __shfl_xor_sync(mask, ss, k, 16);
        outfinal[node * N_CLASS + l16] = v - m - __logf(ss);
    }
}

// ---------------- launch: fork CSR chain onto side stream, join before SpMM ----------------
// k_gemm stays launch #4 (the profiler's capture slot) to verify this round's change.
extern "C" void kernel_launch(void* const* d_in, const int* in_sizes, int n_in,
                              void* d_out, int out_size) {
    const float* x    = (const float*)d_in[0];
    const float* W1   = (const float*)d_in[1];
    const float* W2   = (const float*)d_in[2];
    const int*   esrc = (const int*)d_in[3];
    const int*   edst = (const int*)d_in[4];
    float* out = (float*)d_out;

    static cudaStream_t s2 = nullptr;
    static cudaEvent_t evFork = nullptr, evJoin = nullptr;
    if (s2 == nullptr) {
        cudaStreamCreateWithFlags(&s2, cudaStreamNonBlocking);
        cudaEventCreateWithFlags(&evFork, cudaEventDisableTiming);
        cudaEventCreateWithFlags(&evJoin, cudaEventDisableTiming);
        cudaFuncSetAttribute(k_gemm, cudaFuncAttributeMaxDynamicSharedMemorySize, GEMM_SMEM);
    }

    cudaEventRecord(evFork, 0);
    cudaStreamWaitEvent(s2, evFork, 0);

    // launches 1-2: CSR chain start (side stream)
    k_zero_cnt<<<(N_NODES + 255) / 256, 256, 0, s2>>>();
    k_hist<<<(N_EDGES / 4 + 255) / 256, 256, 0, s2>>>(esrc);

    // launches 3-4: feature chain (main stream) — gemm is launch #4
    k_cvt_w1<<<((N_FEAT / 2) * HIDDEN + 255) / 256, 256>>>(W1);
    k_gemm<<<(N_NODES + GBM - 1) / GBM, 256, GEMM_SMEM>>>(x, W2);

    // launches 5-7: CSR chain rest (side stream)
    k_scan1<<<NCHUNK, 1024, 0, s2>>>();
    k_scan3<<<NCHUNK, 1024, 0, s2>>>();
    k_scatter<<<(N_EDGES / 4 + 255) / 256, 256, 0, s2>>>(esrc, edst);
    cudaEventRecord(evJoin, s2);

    // join, then propagation
    cudaStreamWaitEvent(0, evJoin, 0);
    k_spmm_t<0><<<(N_NODES * N_CLASS + 255) / 256, 256>>>(nullptr);
    k_spmm_t<1><<<(N_NODES * N_CLASS + 255) / 256, 256>>>(out);
}

// round 13
// speedup vs baseline: 1.2422x; 1.2422x over previous
#include <cuda_runtime.h>
#include <cuda_bf16.h>
#include <cuda_fp16.h>
#include <cstdint>

#define N_NODES 100000
#define N_FEAT  512
#define HIDDEN  128
#define N_CLASS 16
#define N_EDGES 3200000
#define ALPHA   0.25f

#define NCHUNK 98   // ceil(100000/1024)

// ---------------- device scratch ----------------
__device__ float  g_local[N_NODES * N_CLASS];      // fp32 local logits (self term)
__device__ __half g_localh[N_NODES * N_CLASS];     // fp16 gather table, iter 1
__device__ __half g_tmph[N_NODES * N_CLASS];       // fp16 gather table, iter 2
__device__ int    g_cnt[N_NODES];
__device__ int    g_rowptr[N_NODES + 1];
__device__ int    g_fill[N_NODES];
__device__ float  g_scale[N_NODES];
__device__ int    g_csr[N_EDGES];
__device__ int    g_chunksum[NCHUNK];
__device__ uint32_t g_W1h[(N_FEAT / 2) * HIDDEN];  // W1 half2, k-pair rows PERMUTED (see k_cvt_w1)

// ---------------- helpers ----------------
__device__ __forceinline__ uint32_t packh(float a, float b) {
    __half2 t = __floats2half2_rn(a, b);
    return *(uint32_t*)&t;
}

__device__ __forceinline__ void mma_f16(float* d, const uint32_t* a,
                                        uint32_t b0, uint32_t b1) {
    asm volatile(
        "mma.sync.aligned.m16n8k16.row.col.f32.f16.f16.f32 "
        "{%0,%1,%2,%3},{%4,%5,%6,%7},{%8,%9},{%0,%1,%2,%3};\n"
        : "+f"(d[0]), "+f"(d[1]), "+f"(d[2]), "+f"(d[3])
        : "r"(a[0]), "r"(a[1]), "r"(a[2]), "r"(a[3]), "r"(b0), "r"(b1));
}

__device__ __forceinline__ void cp16(uint32_t dst, const void* src) {
    asm volatile("cp.async.cg.shared.global [%0], [%1], 16;\n"
                 :: "r"(dst), "l"(src) : "memory");
}
#define CP_COMMIT asm volatile("cp.async.commit_group;\n" ::: "memory")
#define CP_WAIT(N) asm volatile("cp.async.wait_group %0;\n" :: "n"(N) : "memory")

// ---------------- W1 pre-conversion with k-pair permutation ----------------
// Stored k-pair row s (p = s%8 within its 8-row group) holds LOGICAL k-pair
//   l = base + (p<4 ? 2p : 2(p-4)+1)   -> rows {0..7} hold logical {0,2,4,6,1,3,5,7}
// so that mma b0 (row tig) carries logical pair 2tig and b1 (row 4+tig) carries
// 2tig+1, matching A fragments loaded as CONTIGUOUS logical k 4tig..4tig+3.
__global__ void k_cvt_w1(const float* __restrict__ W1) {
    int i = blockIdx.x * blockDim.x + threadIdx.x;
    if (i < (N_FEAT / 2) * HIDDEN) {
        int s = i / HIDDEN;       // stored k-pair row
        int n = i % HIDDEN;
        int p = s & 7;
        int base = s & ~7;
        int l = base + ((p < 4) ? (2 * p) : (2 * (p - 4) + 1));
        g_W1h[i] = packh(W1[(2 * l) * HIDDEN + n], W1[(2 * l + 1) * HIDDEN + n]);
    }
}

// ---------------- CSR build ----------------
__global__ void k_zero_cnt() {
    int i = blockIdx.x * blockDim.x + threadIdx.x;
    if (i < N_NODES) g_cnt[i] = 0;
    if (i == 0) g_rowptr[N_NODES] = N_EDGES;
}

__global__ void k_hist(const int* __restrict__ esrc) {
    int t = blockIdx.x * blockDim.x + threadIdx.x;
    if (t < N_EDGES / 4) {
        int4 s = ((const int4*)esrc)[t];
        atomicAdd(&g_cnt[s.x], 1);
        atomicAdd(&g_cnt[s.y], 1);
        atomicAdd(&g_cnt[s.z], 1);
        atomicAdd(&g_cnt[s.w], 1);
    }
}

__global__ void k_scan1() {
    __shared__ int ws[32];
    int tid = threadIdx.x, lane = tid & 31, wid = tid >> 5;
    int i = blockIdx.x * 1024 + tid;
    int v = (i < N_NODES) ? g_cnt[i] : 0;
    #pragma unroll
    for (int d = 16; d >= 1; d >>= 1) v += __shfl_xor_sync(0xffffffffu, v, d);
    if (lane == 0) ws[wid] = v;
    __syncthreads();
    if (wid == 0) {
        int s = ws[lane];
        #pragma unroll
        for (int d = 16; d >= 1; d >>= 1) s += __shfl_xor_sync(0xffffffffu, s, d);
        if (lane == 0) g_chunksum[blockIdx.x] = s;
    }
}

__global__ void k_scan3() {
    __shared__ int ws[32];
    __shared__ int s_pre[4];
    int tid = threadIdx.x, lane = tid & 31, wid = tid >> 5;

    if (tid < 128) {
        int vp = (tid < blockIdx.x) ? g_chunksum[tid] : 0;
        #pragma unroll
        for (int d = 16; d >= 1; d >>= 1) vp += __shfl_xor_sync(0xffffffffu, vp, d);
        if (lane == 0) s_pre[wid] = vp;
    }

    int i = blockIdx.x * 1024 + tid;
    int v = (i < N_NODES) ? g_cnt[i] : 0;
    int x = v;
    #pragma unroll
    for (int d = 1; d < 32; d <<= 1) {
        int y = __shfl_up_sync(0xffffffffu, x, d);
        if (lane >= d) x += y;
    }
    if (lane == 31) ws[wid] = x;
    __syncthreads();
    if (wid == 0) {
        int w = ws[lane];
        int xs = w;
        #pragma unroll
        for (int d = 1; d < 32; d <<= 1) {
            int y = __shfl_up_sync(0xffffffffu, xs, d);
            if (lane >= d) xs += y;
        }
        ws[lane] = xs;
    }
    __syncthreads();
    int coff = s_pre[0] + s_pre[1] + s_pre[2] + s_pre[3];
    int warp_prefix = (wid > 0) ? ws[wid - 1] : 0;
    int excl = x - v + warp_prefix + coff;
    if (i < N_NODES) {
        g_rowptr[i] = excl;
        g_fill[i]   = excl;
        g_scale[i]  = (1.0f - ALPHA) / fmaxf((float)v, 1e-12f);
    }
}

__global__ void k_scatter(const int* __restrict__ esrc, const int* __restrict__ edst) {
    int t = blockIdx.x * blockDim.x + threadIdx.x;
    if (t < N_EDGES / 4) {
        int4 s = ((const int4*)esrc)[t];
        int4 d = ((const int4*)edst)[t];
        int p;
        p = atomicAdd(&g_fill[s.x], 1); g_csr[p] = d.x;
        p = atomicAdd(&g_fill[s.y], 1); g_csr[p] = d.y;
        p = atomicAdd(&g_fill[s.z], 1); g_csr[p] = d.z;
        p = atomicAdd(&g_fill[s.w], 1); g_csr[p] = d.w;
    }
}

// ---------------- fused GEMM: local = relu(x@W1) @ W2, fp16 MMA ----------------
// BM=128, BN=128, BK=32, 256 thr = 8 warps (4m x 2n), warp tile 32x64.
// A fragments: ONE conflict-free LDS.128 per (row, k16-step) thanks to the
// k-pair permutation in g_W1h. ASTR=48 makes LDS.128 bank-conflict-free.
#define GBM 128
#define GBK 32
#define ASTR 48
#define BSTR 136
#define A_BYTES (GBM * ASTR * 4)            // 24576
#define B_BYTES (16 * BSTR * 4)             // 8704 (16 k-pair rows)
#define STAGE_BYTES (A_BYTES + B_BYTES)     // 33280
#define W2_OFF (2 * STAGE_BYTES)            // 66560
#define OUTS_OFF (W2_OFF + HIDDEN * N_CLASS * 4)  // 74752
#define OUTSTR 17
#define GEMM_SMEM (OUTS_OFF + GBM * OUTSTR * 4)   // 83456
#define HIDSTR 129
#define NKITER (N_FEAT / GBK)               // 16

__global__ __launch_bounds__(256, 2) void k_gemm(const float* __restrict__ x,
                                                 const float* __restrict__ W2) {
    extern __shared__ __align__(16) char sm[];
    float* W2s  = (float*)(sm + W2_OFF);
    float* outS = (float*)(sm + OUTS_OFF);
    float* hid  = (float*)sm;
    uint32_t smem_u32 = (uint32_t)__cvta_generic_to_shared(sm);

    int tid  = threadIdx.x;
    int lane = tid & 31;
    int warp = tid >> 5;
    int blockRow = blockIdx.x * GBM;

    int warpM = warp >> 1;   // 0..3
    int warpN = warp & 1;    // 0..1
    int grp = lane >> 2;     // 0..7
    int tig = lane & 3;      // 0..3

    for (int i = tid; i < HIDDEN * N_CLASS; i += 256) W2s[i] = W2[i];

    float acc[2][8][4];
    #pragma unroll
    for (int mt = 0; mt < 2; mt++)
        #pragma unroll
        for (int nt = 0; nt < 8; nt++)
            #pragma unroll
            for (int r = 0; r < 4; r++) acc[mt][nt][r] = 0.0f;

    auto load_tiles = [&](int kiter, int st) {
        int k0 = kiter * GBK;
        uint32_t abase = smem_u32 + st * STAGE_BYTES;
        uint32_t bbase = abase + A_BYTES;
        // A: 128 rows x 8 granules (32 floats), stride ASTR=48 words
        #pragma unroll
        for (int it = 0; it < 4; it++) {
            int idx = tid + it * 256;
            int r = idx >> 3, c4 = idx & 7;
            int gr = blockRow + r;
            if (gr >= N_NODES) gr = N_NODES - 1;
            cp16(abase + (r * ASTR + c4 * 4) * 4,
                 &x[(size_t)gr * N_FEAT + k0 + c4 * 4]);
        }
        // B: 16 k-pair rows (already permuted in g_W1h) x 32 float4
        #pragma unroll
        for (int it = 0; it < 2; it++) {
            int idx = tid + it * 256;
            int r = idx >> 5, c4 = idx & 31;
            cp16(bbase + (r * BSTR + c4 * 4) * 4,
                 &g_W1h[(kiter * 16 + r) * HIDDEN + c4 * 4]);
        }
    };

    auto compute = [&](int st) {
        const float*    As = (const float*)(sm + st * STAGE_BYTES);
        const uint32_t* Bs = (const uint32_t*)(sm + st * STAGE_BYTES + A_BYTES);
        #pragma unroll
        for (int ks = 0; ks < 2; ks++) {       // two k16 steps per 32-k tile
            uint32_t a[2][4];
            #pragma unroll
            for (int mt = 0; mt < 2; mt++) {
                int r0 = warpM * 32 + mt * 16 + grp;
                // contiguous logical k 4tig..4tig+3 (permutation handles hw order)
                float4 f0 = *(const float4*)&As[r0 * ASTR + ks * 16 + 4 * tig];
                float4 f1 = *(const float4*)&As[(r0 + 8) * ASTR + ks * 16 + 4 * tig];
                a[mt][0] = packh(f0.x, f0.y);   // logical kpair 2tig   (hw lo)
                a[mt][1] = packh(f1.x, f1.y);
                a[mt][2] = packh(f0.z, f0.w);   // logical kpair 2tig+1 (hw hi)
                a[mt][3] = packh(f1.z, f1.w);
            }
            #pragma unroll
            for (int nt = 0; nt < 8; nt++) {
                int col = warpN * 64 + nt * 8 + grp;
                uint32_t b0 = Bs[(ks * 8 + tig) * BSTR + col];       // logical 2tig
                uint32_t b1 = Bs[(ks * 8 + 4 + tig) * BSTR + col];   // logical 2tig+1
                mma_f16(acc[0][nt], a[0], b0, b1);
                mma_f16(acc[1][nt], a[1], b0, b1);
            }
        }
    };

    // 2-stage double buffering (proven round-10 structure)
    load_tiles(0, 0);
    CP_COMMIT;
    #pragma unroll 1
    for (int i = 0; i < NKITER; i++) {
        int st = i & 1;
        if (i + 1 < NKITER) {
            load_tiles(i + 1, st ^ 1);
            CP_COMMIT;
            CP_WAIT(1);
        } else {
            CP_WAIT(0);
        }
        __syncthreads();
        compute(st);
        __syncthreads();
    }

    // relu -> hid
    #pragma unroll
    for (int mt = 0; mt < 2; mt++) {
        int r0 = warpM * 32 + mt * 16 + grp;
        #pragma unroll
        for (int nt = 0; nt < 8; nt++) {
            int c = warpN * 64 + nt * 8 + tig * 2;
            hid[r0 * HIDSTR + c]           = fmaxf(acc[mt][nt][0], 0.f);
            hid[r0 * HIDSTR + c + 1]       = fmaxf(acc[mt][nt][1], 0.f);
            hid[(r0 + 8) * HIDSTR + c]     = fmaxf(acc[mt][nt][2], 0.f);
            hid[(r0 + 8) * HIDSTR + c + 1] = fmaxf(acc[mt][nt][3], 0.f);
        }
    }
    __syncthreads();

    // second gemm: out[128][16] = hid[128][128] @ W2[128][16], 2-way h split
    int r = tid & 127;
    int q = tid >> 7;  // 0..1
    float o[N_CLASS];
    #pragma unroll
    for (int c = 0; c < N_CLASS; c++) o[c] = 0.f;
    int h0 = q * 64;
    #pragma unroll 4
    for (int h = h0; h < h0 + 64; h++) {
        float v = hid[r * HIDSTR + h];
        #pragma unroll
        for (int c = 0; c < N_CLASS; c++) o[c] += v * W2s[h * N_CLASS + c];
    }
    if (q == 0) {
        #pragma unroll
        for (int c = 0; c < N_CLASS; c++) outS[r * OUTSTR + c] = o[c];
    }
    __syncthreads();
    if (q == 1) {
        int gr = blockRow + r;
        if (gr < N_NODES) {
            float vv[N_CLASS];
            #pragma unroll
            for (int c = 0; c < N_CLASS; c++) vv[c] = outS[r * OUTSTR + c] + o[c];
            #pragma unroll
            for (int j = 0; j < 4; j++) {
                float4 v4 = make_float4(vv[j*4+0], vv[j*4+1], vv[j*4+2], vv[j*4+3]);
                *(float4*)&g_local[gr * N_CLASS + j * 4] = v4;
            }
            uint4 h0v, h1v;
            h0v.x = packh(vv[0],  vv[1]);  h0v.y = packh(vv[2],  vv[3]);
            h0v.z = packh(vv[4],  vv[5]);  h0v.w = packh(vv[6],  vv[7]);
            h1v.x = packh(vv[8],  vv[9]);  h1v.y = packh(vv[10], vv[11]);
            h1v.z = packh(vv[12], vv[13]); h1v.w = packh(vv[14], vv[15]);
            *(uint4*)&g_localh[gr * N_CLASS]     = h0v;
            *(uint4*)&g_localh[gr * N_CLASS + 8] = h1v;
        }
    }
}

// ---------------- SpMM: 16 lanes = 16 classes per node, fp16 gather tables ----------------
template<int PHASE>
__global__ void k_spmm_t(float* __restrict__ outfinal) {
    const __half* tbl = (PHASE == 0) ? g_localh : g_tmph;
    int t = blockIdx.x * blockDim.x + threadIdx.x;
    int node = t >> 4;
    if (node >= N_NODES) return;
    int l16 = threadIdx.x & 15;
    unsigned mask = 0xFFFFu << (threadIdx.x & 16);

    int s = g_rowptr[node], e = g_rowptr[node + 1];
    float a = 0.f;
    int i = s;
    for (; i + 16 <= e; i += 16) {
        int idx = __ldg(&g_csr[i + l16]);
        #pragma unroll
        for (int q = 0; q < 16; q++) {
            int j = __shfl_sync(mask, idx, q, 16);
            a += __half2float(__ldg(&tbl[j * N_CLASS + l16]));
        }
    }
    int rem = e - i;
    if (rem) {
        int idx = (l16 < rem) ? __ldg(&g_csr[i + l16]) : 0;
        for (int q = 0; q < rem; q++) {
            int j = __shfl_sync(mask, idx, q, 16);
            a += __half2float(__ldg(&tbl[j * N_CLASS + l16]));
        }
    }
    float v = g_scale[node] * a + ALPHA * g_local[node * N_CLASS + l16];

    if (PHASE == 0) {
        g_tmph[node * N_CLASS + l16] = __float2half_rn(v);
    } else {
        float m = v;
        #pragma unroll
        for (int k = 8; k >= 1; k >>= 1) m = fmaxf(m, __shfl_xor_sync(mask, m, k, 16));
        float ex = __expf(v - m);
        float ss = ex;
        #pragma unroll
        for (int k = 8; k >= 1; k >>= 1) ss += __shfl_xor_sync(mask, ss, k, 16);
        outfinal[node * N_CLASS + l16] = v - m - __logf(ss);
    }
}

// ---------------- launch: fork CSR chain onto side stream, join before SpMM ----------------
// k_gemm stays launch #4 (the profiler's capture slot) to verify this round's change.
extern "C" void kernel_launch(void* const* d_in, const int* in_sizes, int n_in,
                              void* d_out, int out_size) {
    const float* x    = (const float*)d_in[0];
    const float* W1   = (const float*)d_in[1];
    const float* W2   = (const float*)d_in[2];
    const int*   esrc = (const int*)d_in[3];
    const int*   edst = (const int*)d_in[4];
    float* out = (float*)d_out;

    static cudaStream_t s2 = nullptr;
    static cudaEvent_t evFork = nullptr, evJoin = nullptr;
    if (s2 == nullptr) {
        cudaStreamCreateWithFlags(&s2, cudaStreamNonBlocking);
        cudaEventCreateWithFlags(&evFork, cudaEventDisableTiming);
        cudaEventCreateWithFlags(&evJoin, cudaEventDisableTiming);
        cudaFuncSetAttribute(k_gemm, cudaFuncAttributeMaxDynamicSharedMemorySize, GEMM_SMEM);
    }

    cudaEventRecord(evFork, 0);
    cudaStreamWaitEvent(s2, evFork, 0);

    // launches 1-2: CSR chain start (side stream)
    k_zero_cnt<<<(N_NODES + 255) / 256, 256, 0, s2>>>();
    k_hist<<<(N_EDGES / 4 + 255) / 256, 256, 0, s2>>>(esrc);

    // launches 3-4: feature chain (main stream) — gemm is launch #4
    k_cvt_w1<<<((N_FEAT / 2) * HIDDEN + 255) / 256, 256>>>(W1);
    k_gemm<<<(N_NODES + GBM - 1) / GBM, 256, GEMM_SMEM>>>(x, W2);

    // launches 5-7: CSR chain rest (side stream)
    k_scan1<<<NCHUNK, 1024, 0, s2>>>();
    k_scan3<<<NCHUNK, 1024, 0, s2>>>();
    k_scatter<<<(N_EDGES / 4 + 255) / 256, 256, 0, s2>>>(esrc, edst);
    cudaEventRecord(evJoin, s2);

    // join, then propagation
    cudaStreamWaitEvent(0, evJoin, 0);
    k_spmm_t<0><<<(N_NODES * N_CLASS + 255) / 256, 256>>>(nullptr);
    k_spmm_t<1><<<(N_NODES * N_CLASS + 255) / 256, 256>>>(out);
}

// round 14
// speedup vs baseline: 1.2788x; 1.0294x over previous
#include <cuda_runtime.h>
#include <cuda_bf16.h>
#include <cuda_fp16.h>
#include <cstdint>

#define N_NODES 100000
#define N_FEAT  512
#define HIDDEN  128
#define N_CLASS 16
#define N_EDGES 3200000
#define ALPHA   0.25f

#define NCHUNK 98   // ceil(100000/1024)

// ---------------- device scratch ----------------
__device__ float  g_local[N_NODES * N_CLASS];      // fp32 local logits (self term)
__device__ __half g_localh[N_NODES * N_CLASS];     // fp16 gather table, iter 1
__device__ __half g_tmph[N_NODES * N_CLASS];       // fp16 gather table, iter 2
__device__ int    g_cnt[N_NODES];
__device__ int    g_rowptr[N_NODES + 1];
__device__ int    g_fill[N_NODES];
__device__ float  g_scale[N_NODES];
__device__ int    g_csr[N_EDGES];
__device__ int    g_chunksum[NCHUNK];
__device__ uint32_t g_W1h[(N_FEAT / 2) * HIDDEN];  // W1 half2, k-pair rows PERMUTED (see k_cvt_w1)

// ---------------- helpers ----------------
__device__ __forceinline__ uint32_t packh(float a, float b) {
    __half2 t = __floats2half2_rn(a, b);
    return *(uint32_t*)&t;
}

__device__ __forceinline__ void mma_f16(float* d, const uint32_t* a,
                                        uint32_t b0, uint32_t b1) {
    asm volatile(
        "mma.sync.aligned.m16n8k16.row.col.f32.f16.f16.f32 "
        "{%0,%1,%2,%3},{%4,%5,%6,%7},{%8,%9},{%0,%1,%2,%3};\n"
        : "+f"(d[0]), "+f"(d[1]), "+f"(d[2]), "+f"(d[3])
        : "r"(a[0]), "r"(a[1]), "r"(a[2]), "r"(a[3]), "r"(b0), "r"(b1));
}

__device__ __forceinline__ void cp16(uint32_t dst, const void* src) {
    asm volatile("cp.async.cg.shared.global [%0], [%1], 16;\n"
                 :: "r"(dst), "l"(src) : "memory");
}
#define CP_COMMIT asm volatile("cp.async.commit_group;\n" ::: "memory")
#define CP_WAIT(N) asm volatile("cp.async.wait_group %0;\n" :: "n"(N) : "memory")

// ---------------- W1 pre-conversion with k-pair permutation ----------------
// Stored k-pair row s (p = s%8) holds LOGICAL k-pair l = base + (p<4 ? 2p : 2(p-4)+1)
// so mma b0/b1 line up with A fragments loaded as CONTIGUOUS logical k.
__global__ void k_cvt_w1(const float* __restrict__ W1) {
    int i = blockIdx.x * blockDim.x + threadIdx.x;
    if (i < (N_FEAT / 2) * HIDDEN) {
        int s = i / HIDDEN;       // stored k-pair row
        int n = i % HIDDEN;
        int p = s & 7;
        int base = s & ~7;
        int l = base + ((p < 4) ? (2 * p) : (2 * (p - 4) + 1));
        g_W1h[i] = packh(W1[(2 * l) * HIDDEN + n], W1[(2 * l + 1) * HIDDEN + n]);
    }
}

// ---------------- CSR build ----------------
__global__ void k_zero_cnt() {
    int i = blockIdx.x * blockDim.x + threadIdx.x;
    if (i < N_NODES) g_cnt[i] = 0;
    if (i == 0) g_rowptr[N_NODES] = N_EDGES;
}

__global__ void k_hist(const int* __restrict__ esrc) {
    int t = blockIdx.x * blockDim.x + threadIdx.x;
    if (t < N_EDGES / 4) {
        int4 s = ((const int4*)esrc)[t];
        atomicAdd(&g_cnt[s.x], 1);
        atomicAdd(&g_cnt[s.y], 1);
        atomicAdd(&g_cnt[s.z], 1);
        atomicAdd(&g_cnt[s.w], 1);
    }
}

__global__ void k_scan1() {
    __shared__ int ws[32];
    int tid = threadIdx.x, lane = tid & 31, wid = tid >> 5;
    int i = blockIdx.x * 1024 + tid;
    int v = (i < N_NODES) ? g_cnt[i] : 0;
    #pragma unroll
    for (int d = 16; d >= 1; d >>= 1) v += __shfl_xor_sync(0xffffffffu, v, d);
    if (lane == 0) ws[wid] = v;
    __syncthreads();
    if (wid == 0) {
        int s = ws[lane];
        #pragma unroll
        for (int d = 16; d >= 1; d >>= 1) s += __shfl_xor_sync(0xffffffffu, s, d);
        if (lane == 0) g_chunksum[blockIdx.x] = s;
    }
}

__global__ void k_scan3() {
    __shared__ int ws[32];
    __shared__ int s_pre[4];
    int tid = threadIdx.x, lane = tid & 31, wid = tid >> 5;

    if (tid < 128) {
        int vp = (tid < blockIdx.x) ? g_chunksum[tid] : 0;
        #pragma unroll
        for (int d = 16; d >= 1; d >>= 1) vp += __shfl_xor_sync(0xffffffffu, vp, d);
        if (lane == 0) s_pre[wid] = vp;
    }

    int i = blockIdx.x * 1024 + tid;
    int v = (i < N_NODES) ? g_cnt[i] : 0;
    int x = v;
    #pragma unroll
    for (int d = 1; d < 32; d <<= 1) {
        int y = __shfl_up_sync(0xffffffffu, x, d);
        if (lane >= d) x += y;
    }
    if (lane == 31) ws[wid] = x;
    __syncthreads();
    if (wid == 0) {
        int w = ws[lane];
        int xs = w;
        #pragma unroll
        for (int d = 1; d < 32; d <<= 1) {
            int y = __shfl_up_sync(0xffffffffu, xs, d);
            if (lane >= d) xs += y;
        }
        ws[lane] = xs;
    }
    __syncthreads();
    int coff = s_pre[0] + s_pre[1] + s_pre[2] + s_pre[3];
    int warp_prefix = (wid > 0) ? ws[wid - 1] : 0;
    int excl = x - v + warp_prefix + coff;
    if (i < N_NODES) {
        g_rowptr[i] = excl;
        g_fill[i]   = excl;
        g_scale[i]  = (1.0f - ALPHA) / fmaxf((float)v, 1e-12f);
    }
}

__global__ void k_scatter(const int* __restrict__ esrc, const int* __restrict__ edst) {
    int t = blockIdx.x * blockDim.x + threadIdx.x;
    if (t < N_EDGES / 4) {
        int4 s = ((const int4*)esrc)[t];
        int4 d = ((const int4*)edst)[t];
        int p;
        p = atomicAdd(&g_fill[s.x], 1); g_csr[p] = d.x;
        p = atomicAdd(&g_fill[s.y], 1); g_csr[p] = d.y;
        p = atomicAdd(&g_fill[s.z], 1); g_csr[p] = d.z;
        p = atomicAdd(&g_fill[s.w], 1); g_csr[p] = d.w;
    }
}

// ---------------- fused GEMM: local = relu(x@W1) @ W2, fp16 MMA (round-13 winner) ----------------
#define GBM 128
#define GBK 32
#define ASTR 48
#define BSTR 136
#define A_BYTES (GBM * ASTR * 4)            // 24576
#define B_BYTES (16 * BSTR * 4)             // 8704
#define STAGE_BYTES (A_BYTES + B_BYTES)     // 33280
#define W2_OFF (2 * STAGE_BYTES)            // 66560
#define OUTS_OFF (W2_OFF + HIDDEN * N_CLASS * 4)  // 74752
#define OUTSTR 17
#define GEMM_SMEM (OUTS_OFF + GBM * OUTSTR * 4)   // 83456
#define HIDSTR 129
#define NKITER (N_FEAT / GBK)               // 16

__global__ __launch_bounds__(256, 2) void k_gemm(const float* __restrict__ x,
                                                 const float* __restrict__ W2) {
    extern __shared__ __align__(16) char sm[];
    float* W2s  = (float*)(sm + W2_OFF);
    float* outS = (float*)(sm + OUTS_OFF);
    float* hid  = (float*)sm;
    uint32_t smem_u32 = (uint32_t)__cvta_generic_to_shared(sm);

    int tid  = threadIdx.x;
    int lane = tid & 31;
    int warp = tid >> 5;
    int blockRow = blockIdx.x * GBM;

    int warpM = warp >> 1;   // 0..3
    int warpN = warp & 1;    // 0..1
    int grp = lane >> 2;     // 0..7
    int tig = lane & 3;      // 0..3

    for (int i = tid; i < HIDDEN * N_CLASS; i += 256) W2s[i] = W2[i];

    float acc[2][8][4];
    #pragma unroll
    for (int mt = 0; mt < 2; mt++)
        #pragma unroll
        for (int nt = 0; nt < 8; nt++)
            #pragma unroll
            for (int r = 0; r < 4; r++) acc[mt][nt][r] = 0.0f;

    auto load_tiles = [&](int kiter, int st) {
        int k0 = kiter * GBK;
        uint32_t abase = smem_u32 + st * STAGE_BYTES;
        uint32_t bbase = abase + A_BYTES;
        #pragma unroll
        for (int it = 0; it < 4; it++) {
            int idx = tid + it * 256;
            int r = idx >> 3, c4 = idx & 7;
            int gr = blockRow + r;
            if (gr >= N_NODES) gr = N_NODES - 1;
            cp16(abase + (r * ASTR + c4 * 4) * 4,
                 &x[(size_t)gr * N_FEAT + k0 + c4 * 4]);
        }
        #pragma unroll
        for (int it = 0; it < 2; it++) {
            int idx = tid + it * 256;
            int r = idx >> 5, c4 = idx & 31;
            cp16(bbase + (r * BSTR + c4 * 4) * 4,
                 &g_W1h[(kiter * 16 + r) * HIDDEN + c4 * 4]);
        }
    };

    auto compute = [&](int st) {
        const float*    As = (const float*)(sm + st * STAGE_BYTES);
        const uint32_t* Bs = (const uint32_t*)(sm + st * STAGE_BYTES + A_BYTES);
        #pragma unroll
        for (int ks = 0; ks < 2; ks++) {
            uint32_t a[2][4];
            #pragma unroll
            for (int mt = 0; mt < 2; mt++) {
                int r0 = warpM * 32 + mt * 16 + grp;
                float4 f0 = *(const float4*)&As[r0 * ASTR + ks * 16 + 4 * tig];
                float4 f1 = *(const float4*)&As[(r0 + 8) * ASTR + ks * 16 + 4 * tig];
                a[mt][0] = packh(f0.x, f0.y);
                a[mt][1] = packh(f1.x, f1.y);
                a[mt][2] = packh(f0.z, f0.w);
                a[mt][3] = packh(f1.z, f1.w);
            }
            #pragma unroll
            for (int nt = 0; nt < 8; nt++) {
                int col = warpN * 64 + nt * 8 + grp;
                uint32_t b0 = Bs[(ks * 8 + tig) * BSTR + col];
                uint32_t b1 = Bs[(ks * 8 + 4 + tig) * BSTR + col];
                mma_f16(acc[0][nt], a[0], b0, b1);
                mma_f16(acc[1][nt], a[1], b0, b1);
            }
        }
    };

    load_tiles(0, 0);
    CP_COMMIT;
    #pragma unroll 1
    for (int i = 0; i < NKITER; i++) {
        int st = i & 1;
        if (i + 1 < NKITER) {
            load_tiles(i + 1, st ^ 1);
            CP_COMMIT;
            CP_WAIT(1);
        } else {
            CP_WAIT(0);
        }
        __syncthreads();
        compute(st);
        __syncthreads();
    }

    // relu -> hid
    #pragma unroll
    for (int mt = 0; mt < 2; mt++) {
        int r0 = warpM * 32 + mt * 16 + grp;
        #pragma unroll
        for (int nt = 0; nt < 8; nt++) {
            int c = warpN * 64 + nt * 8 + tig * 2;
            hid[r0 * HIDSTR + c]           = fmaxf(acc[mt][nt][0], 0.f);
            hid[r0 * HIDSTR + c + 1]       = fmaxf(acc[mt][nt][1], 0.f);
            hid[(r0 + 8) * HIDSTR + c]     = fmaxf(acc[mt][nt][2], 0.f);
            hid[(r0 + 8) * HIDSTR + c + 1] = fmaxf(acc[mt][nt][3], 0.f);
        }
    }
    __syncthreads();

    // second gemm: out[128][16] = hid[128][128] @ W2[128][16], 2-way h split
    int r = tid & 127;
    int q = tid >> 7;  // 0..1
    float o[N_CLASS];
    #pragma unroll
    for (int c = 0; c < N_CLASS; c++) o[c] = 0.f;
    int h0 = q * 64;
    #pragma unroll 4
    for (int h = h0; h < h0 + 64; h++) {
        float v = hid[r * HIDSTR + h];
        #pragma unroll
        for (int c = 0; c < N_CLASS; c++) o[c] += v * W2s[h * N_CLASS + c];
    }
    if (q == 0) {
        #pragma unroll
        for (int c = 0; c < N_CLASS; c++) outS[r * OUTSTR + c] = o[c];
    }
    __syncthreads();
    if (q == 1) {
        int gr = blockRow + r;
        if (gr < N_NODES) {
            float vv[N_CLASS];
            #pragma unroll
            for (int c = 0; c < N_CLASS; c++) vv[c] = outS[r * OUTSTR + c] + o[c];
            #pragma unroll
            for (int j = 0; j < 4; j++) {
                float4 v4 = make_float4(vv[j*4+0], vv[j*4+1], vv[j*4+2], vv[j*4+3]);
                *(float4*)&g_local[gr * N_CLASS + j * 4] = v4;
            }
            uint4 h0v, h1v;
            h0v.x = packh(vv[0],  vv[1]);  h0v.y = packh(vv[2],  vv[3]);
            h0v.z = packh(vv[4],  vv[5]);  h0v.w = packh(vv[6],  vv[7]);
            h1v.x = packh(vv[8],  vv[9]);  h1v.y = packh(vv[10], vv[11]);
            h1v.z = packh(vv[12], vv[13]); h1v.w = packh(vv[14], vv[15]);
            *(uint4*)&g_localh[gr * N_CLASS]     = h0v;
            *(uint4*)&g_localh[gr * N_CLASS + 8] = h1v;
        }
    }
}

// ---------------- SpMM v2: 16 lanes/node, half2 gathers (8 lanes/edge, 2 edges/step) ----------------
// lane l16: cpair = l16&7 (class pair 2cpair,2cpair+1), sub = l16>>3 (edge parity).
// Per 16-edge block: 8 shfl + 8 LDG.32 + dual float2 accumulators (FADD chain /4).
template<int PHASE>
__global__ void k_spmm_t(float* __restrict__ outfinal) {
    const __half2* tbl = (const __half2*)((PHASE == 0) ? g_localh : g_tmph);
    int t = blockIdx.x * blockDim.x + threadIdx.x;
    int node = t >> 4;
    if (node >= N_NODES) return;
    int l16 = threadIdx.x & 15;
    int cpair = l16 & 7;
    int sub = l16 >> 3;
    unsigned mask = 0xFFFFu << (threadIdx.x & 16);

    int s = g_rowptr[node], e = g_rowptr[node + 1];
    float ax0 = 0.f, ay0 = 0.f, ax1 = 0.f, ay1 = 0.f;
    int i = s;
    for (; i + 16 <= e; i += 16) {
        int idx = __ldg(&g_csr[i + l16]);
        #pragma unroll
        for (int q = 0; q < 8; q += 2) {
            int j0 = __shfl_sync(mask, idx, 2 * q + sub, 16);
            int j1 = __shfl_sync(mask, idx, 2 * (q + 1) + sub, 16);
            float2 f0 = __half22float2(__ldg(&tbl[j0 * 8 + cpair]));
            float2 f1 = __half22float2(__ldg(&tbl[j1 * 8 + cpair]));
            ax0 += f0.x; ay0 += f0.y;
            ax1 += f1.x; ay1 += f1.y;
        }
    }
    int rem = e - i;
    if (rem) {
        int idx = (l16 < rem) ? __ldg(&g_csr[i + l16]) : 0;
        #pragma unroll
        for (int q = 0; q < 8; q++) {
            int src = 2 * q + sub;
            int j = __shfl_sync(mask, idx, src, 16);
            if (src < rem) {
                float2 f = __half22float2(__ldg(&tbl[j * 8 + cpair]));
                ax0 += f.x; ay0 += f.y;
            }
        }
    }
    float ax = ax0 + ax1, ay = ay0 + ay1;
    // fold the two edge-parity sub-groups together (all 16 lanes get the total)
    ax += __shfl_xor_sync(mask, ax, 8, 16);
    ay += __shfl_xor_sync(mask, ay, 8, 16);

    float sc = g_scale[node];
    float2 l2v = *(const float2*)&g_local[node * N_CLASS + 2 * cpair];
    float vx = sc * ax + ALPHA * l2v.x;
    float vy = sc * ay + ALPHA * l2v.y;

    if (PHASE == 0) {
        if (sub == 0)
            ((__half2*)g_tmph)[node * 8 + cpair] = __floats2half2_rn(vx, vy);
    } else {
        float m = fmaxf(vx, vy);
        #pragma unroll
        for (int k = 4; k >= 1; k >>= 1) m = fmaxf(m, __shfl_xor_sync(mask, m, k, 8));
        float ss = __expf(vx - m) + __expf(vy - m);
        #pragma unroll
        for (int k = 4; k >= 1; k >>= 1) ss += __shfl_xor_sync(mask, ss, k, 8);
        if (sub == 0) {
            float lg = __logf(ss);
            float2 o = make_float2(vx - m - lg, vy - m - lg);
            *(float2*)&outfinal[node * N_CLASS + 2 * cpair] = o;
        }
    }
}

// ---------------- launch: fork CSR chain onto side stream, join before SpMM ----------------
// k_gemm stays launch #4 (profiler slot) to confirm no GEMM regression.
extern "C" void kernel_launch(void* const* d_in, const int* in_sizes, int n_in,
                              void* d_out, int out_size) {
    const float* x    = (const float*)d_in[0];
    const float* W1   = (const float*)d_in[1];
    const float* W2   = (const float*)d_in[2];
    const int*   esrc = (const int*)d_in[3];
    const int*   edst = (const int*)d_in[4];
    float* out = (float*)d_out;

    static cudaStream_t s2 = nullptr;
    static cudaEvent_t evFork = nullptr, evJoin = nullptr;
    if (s2 == nullptr) {
        cudaStreamCreateWithFlags(&s2, cudaStreamNonBlocking);
        cudaEventCreateWithFlags(&evFork, cudaEventDisableTiming);
        cudaEventCreateWithFlags(&evJoin, cudaEventDisableTiming);
        cudaFuncSetAttribute(k_gemm, cudaFuncAttributeMaxDynamicSharedMemorySize, GEMM_SMEM);
    }

    cudaEventRecord(evFork, 0);
    cudaStreamWaitEvent(s2, evFork, 0);

    // launches 1-2: CSR chain start (side stream)
    k_zero_cnt<<<(N_NODES + 255) / 256, 256, 0, s2>>>();
    k_hist<<<(N_EDGES / 4 + 255) / 256, 256, 0, s2>>>(esrc);

    // launches 3-4: feature chain (main stream) — gemm is launch #4
    k_cvt_w1<<<((N_FEAT / 2) * HIDDEN + 255) / 256, 256>>>(W1);
    k_gemm<<<(N_NODES + GBM - 1) / GBM, 256, GEMM_SMEM>>>(x, W2);

    // launches 5-7: CSR chain rest (side stream)
    k_scan1<<<NCHUNK, 1024, 0, s2>>>();
    k_scan3<<<NCHUNK, 1024, 0, s2>>>();
    k_scatter<<<(N_EDGES / 4 + 255) / 256, 256, 0, s2>>>(esrc, edst);
    cudaEventRecord(evJoin, s2);

    // join, then propagation
    cudaStreamWaitEvent(0, evJoin, 0);
    k_spmm_t<0><<<(N_NODES * N_CLASS + 255) / 256, 256>>>(nullptr);
    k_spmm_t<1><<<(N_NODES * N_CLASS + 255) / 256, 256>>>(out);
}

// round 15
// speedup vs baseline: 1.3690x; 1.0706x over previous
#include <cuda_runtime.h>
#include <cuda_bf16.h>
#include <cuda_fp16.h>
#include <cstdint>

#define N_NODES 100000
#define N_FEAT  512
#define HIDDEN  128
#define N_CLASS 16
#define N_EDGES 3200000
#define ALPHA   0.25f

#define NCHUNK 98   // ceil(100000/1024)

// ---------------- device scratch ----------------
__device__ float  g_local[N_NODES * N_CLASS];      // fp32 local logits (self term)
__device__ __half g_localh[N_NODES * N_CLASS];     // fp16 gather table, iter 1
__device__ __half g_tmph[N_NODES * N_CLASS];       // fp16 gather table, iter 2
__device__ int    g_cnt[N_NODES];
__device__ int    g_rowptr[N_NODES + 1];
__device__ int    g_fill[N_NODES];
__device__ float  g_scale[N_NODES];
__device__ int    g_csr[N_EDGES];
__device__ int    g_chunksum[NCHUNK];
__device__ uint32_t g_W1h[(N_FEAT / 2) * HIDDEN];  // W1 half2, k-pair rows PERMUTED (see k_cvt_w1)

// ---------------- helpers ----------------
__device__ __forceinline__ uint32_t packh(float a, float b) {
    __half2 t = __floats2half2_rn(a, b);
    return *(uint32_t*)&t;
}

__device__ __forceinline__ void mma_f16(float* d, const uint32_t* a,
                                        uint32_t b0, uint32_t b1) {
    asm volatile(
        "mma.sync.aligned.m16n8k16.row.col.f32.f16.f16.f32 "
        "{%0,%1,%2,%3},{%4,%5,%6,%7},{%8,%9},{%0,%1,%2,%3};\n"
        : "+f"(d[0]), "+f"(d[1]), "+f"(d[2]), "+f"(d[3])
        : "r"(a[0]), "r"(a[1]), "r"(a[2]), "r"(a[3]), "r"(b0), "r"(b1));
}

__device__ __forceinline__ void cp16(uint32_t dst, const void* src) {
    asm volatile("cp.async.cg.shared.global [%0], [%1], 16;\n"
                 :: "r"(dst), "l"(src) : "memory");
}
#define CP_COMMIT asm volatile("cp.async.commit_group;\n" ::: "memory")
#define CP_WAIT(N) asm volatile("cp.async.wait_group %0;\n" :: "n"(N) : "memory")

// ---------------- W1 pre-conversion with k-pair permutation ----------------
__global__ void k_cvt_w1(const float* __restrict__ W1) {
    int i = blockIdx.x * blockDim.x + threadIdx.x;
    if (i < (N_FEAT / 2) * HIDDEN) {
        int s = i / HIDDEN;       // stored k-pair row
        int n = i % HIDDEN;
        int p = s & 7;
        int base = s & ~7;
        int l = base + ((p < 4) ? (2 * p) : (2 * (p - 4) + 1));
        g_W1h[i] = packh(W1[(2 * l) * HIDDEN + n], W1[(2 * l + 1) * HIDDEN + n]);
    }
}

// ---------------- CSR build ----------------
__global__ void k_zero_cnt() {
    int i = blockIdx.x * blockDim.x + threadIdx.x;
    if (i < N_NODES) g_cnt[i] = 0;
    if (i == 0) g_rowptr[N_NODES] = N_EDGES;
}

__global__ void k_hist(const int* __restrict__ esrc) {
    int t = blockIdx.x * blockDim.x + threadIdx.x;
    if (t < N_EDGES / 4) {
        int4 s = ((const int4*)esrc)[t];
        atomicAdd(&g_cnt[s.x], 1);
        atomicAdd(&g_cnt[s.y], 1);
        atomicAdd(&g_cnt[s.z], 1);
        atomicAdd(&g_cnt[s.w], 1);
    }
}

__global__ void k_scan1() {
    __shared__ int ws[32];
    int tid = threadIdx.x, lane = tid & 31, wid = tid >> 5;
    int i = blockIdx.x * 1024 + tid;
    int v = (i < N_NODES) ? g_cnt[i] : 0;
    #pragma unroll
    for (int d = 16; d >= 1; d >>= 1) v += __shfl_xor_sync(0xffffffffu, v, d);
    if (lane == 0) ws[wid] = v;
    __syncthreads();
    if (wid == 0) {
        int s = ws[lane];
        #pragma unroll
        for (int d = 16; d >= 1; d >>= 1) s += __shfl_xor_sync(0xffffffffu, s, d);
        if (lane == 0) g_chunksum[blockIdx.x] = s;
    }
}

__global__ void k_scan3() {
    __shared__ int ws[32];
    __shared__ int s_pre[4];
    int tid = threadIdx.x, lane = tid & 31, wid = tid >> 5;

    if (tid < 128) {
        int vp = (tid < blockIdx.x) ? g_chunksum[tid] : 0;
        #pragma unroll
        for (int d = 16; d >= 1; d >>= 1) vp += __shfl_xor_sync(0xffffffffu, vp, d);
        if (lane == 0) s_pre[wid] = vp;
    }

    int i = blockIdx.x * 1024 + tid;
    int v = (i < N_NODES) ? g_cnt[i] : 0;
    int x = v;
    #pragma unroll
    for (int d = 1; d < 32; d <<= 1) {
        int y = __shfl_up_sync(0xffffffffu, x, d);
        if (lane >= d) x += y;
    }
    if (lane == 31) ws[wid] = x;
    __syncthreads();
    if (wid == 0) {
        int w = ws[lane];
        int xs = w;
        #pragma unroll
        for (int d = 1; d < 32; d <<= 1) {
            int y = __shfl_up_sync(0xffffffffu, xs, d);
            if (lane >= d) xs += y;
        }
        ws[lane] = xs;
    }
    __syncthreads();
    int coff = s_pre[0] + s_pre[1] + s_pre[2] + s_pre[3];
    int warp_prefix = (wid > 0) ? ws[wid - 1] : 0;
    int excl = x - v + warp_prefix + coff;
    if (i < N_NODES) {
        g_rowptr[i] = excl;
        g_fill[i]   = excl;
        g_scale[i]  = (1.0f - ALPHA) / fmaxf((float)v, 1e-12f);
    }
}

__global__ void k_scatter(const int* __restrict__ esrc, const int* __restrict__ edst) {
    int t = blockIdx.x * blockDim.x + threadIdx.x;
    if (t < N_EDGES / 4) {
        int4 s = ((const int4*)esrc)[t];
        int4 d = ((const int4*)edst)[t];
        int p;
        p = atomicAdd(&g_fill[s.x], 1); g_csr[p] = d.x;
        p = atomicAdd(&g_fill[s.y], 1); g_csr[p] = d.y;
        p = atomicAdd(&g_fill[s.z], 1); g_csr[p] = d.z;
        p = atomicAdd(&g_fill[s.w], 1); g_csr[p] = d.w;
    }
}

// ---------------- fused GEMM: local = relu(x@W1) @ W2, fp16 MMA (round-13 winner) ----------------
#define GBM 128
#define GBK 32
#define ASTR 48
#define BSTR 136
#define A_BYTES (GBM * ASTR * 4)            // 24576
#define B_BYTES (16 * BSTR * 4)             // 8704
#define STAGE_BYTES (A_BYTES + B_BYTES)     // 33280
#define W2_OFF (2 * STAGE_BYTES)            // 66560
#define OUTS_OFF (W2_OFF + HIDDEN * N_CLASS * 4)  // 74752
#define OUTSTR 17
#define GEMM_SMEM (OUTS_OFF + GBM * OUTSTR * 4)   // 83456
#define HIDSTR 129
#define NKITER (N_FEAT / GBK)               // 16

__global__ __launch_bounds__(256, 2) void k_gemm(const float* __restrict__ x,
                                                 const float* __restrict__ W2) {
    extern __shared__ __align__(16) char sm[];
    float* W2s  = (float*)(sm + W2_OFF);
    float* outS = (float*)(sm + OUTS_OFF);
    float* hid  = (float*)sm;
    uint32_t smem_u32 = (uint32_t)__cvta_generic_to_shared(sm);

    int tid  = threadIdx.x;
    int lane = tid & 31;
    int warp = tid >> 5;
    int blockRow = blockIdx.x * GBM;

    int warpM = warp >> 1;   // 0..3
    int warpN = warp & 1;    // 0..1
    int grp = lane >> 2;     // 0..7
    int tig = lane & 3;      // 0..3

    for (int i = tid; i < HIDDEN * N_CLASS; i += 256) W2s[i] = W2[i];

    float acc[2][8][4];
    #pragma unroll
    for (int mt = 0; mt < 2; mt++)
        #pragma unroll
        for (int nt = 0; nt < 8; nt++)
            #pragma unroll
            for (int r = 0; r < 4; r++) acc[mt][nt][r] = 0.0f;

    auto load_tiles = [&](int kiter, int st) {
        int k0 = kiter * GBK;
        uint32_t abase = smem_u32 + st * STAGE_BYTES;
        uint32_t bbase = abase + A_BYTES;
        #pragma unroll
        for (int it = 0; it < 4; it++) {
            int idx = tid + it * 256;
            int r = idx >> 3, c4 = idx & 7;
            int gr = blockRow + r;
            if (gr >= N_NODES) gr = N_NODES - 1;
            cp16(abase + (r * ASTR + c4 * 4) * 4,
                 &x[(size_t)gr * N_FEAT + k0 + c4 * 4]);
        }
        #pragma unroll
        for (int it = 0; it < 2; it++) {
            int idx = tid + it * 256;
            int r = idx >> 5, c4 = idx & 31;
            cp16(bbase + (r * BSTR + c4 * 4) * 4,
                 &g_W1h[(kiter * 16 + r) * HIDDEN + c4 * 4]);
        }
    };

    auto compute = [&](int st) {
        const float*    As = (const float*)(sm + st * STAGE_BYTES);
        const uint32_t* Bs = (const uint32_t*)(sm + st * STAGE_BYTES + A_BYTES);
        #pragma unroll
        for (int ks = 0; ks < 2; ks++) {
            uint32_t a[2][4];
            #pragma unroll
            for (int mt = 0; mt < 2; mt++) {
                int r0 = warpM * 32 + mt * 16 + grp;
                float4 f0 = *(const float4*)&As[r0 * ASTR + ks * 16 + 4 * tig];
                float4 f1 = *(const float4*)&As[(r0 + 8) * ASTR + ks * 16 + 4 * tig];
                a[mt][0] = packh(f0.x, f0.y);
                a[mt][1] = packh(f1.x, f1.y);
                a[mt][2] = packh(f0.z, f0.w);
                a[mt][3] = packh(f1.z, f1.w);
            }
            #pragma unroll
            for (int nt = 0; nt < 8; nt++) {
                int col = warpN * 64 + nt * 8 + grp;
                uint32_t b0 = Bs[(ks * 8 + tig) * BSTR + col];
                uint32_t b1 = Bs[(ks * 8 + 4 + tig) * BSTR + col];
                mma_f16(acc[0][nt], a[0], b0, b1);
                mma_f16(acc[1][nt], a[1], b0, b1);
            }
        }
    };

    load_tiles(0, 0);
    CP_COMMIT;
    #pragma unroll 1
    for (int i = 0; i < NKITER; i++) {
        int st = i & 1;
        if (i + 1 < NKITER) {
            load_tiles(i + 1, st ^ 1);
            CP_COMMIT;
            CP_WAIT(1);
        } else {
            CP_WAIT(0);
        }
        __syncthreads();
        compute(st);
        __syncthreads();
    }

    // relu -> hid
    #pragma unroll
    for (int mt = 0; mt < 2; mt++) {
        int r0 = warpM * 32 + mt * 16 + grp;
        #pragma unroll
        for (int nt = 0; nt < 8; nt++) {
            int c = warpN * 64 + nt * 8 + tig * 2;
            hid[r0 * HIDSTR + c]           = fmaxf(acc[mt][nt][0], 0.f);
            hid[r0 * HIDSTR + c + 1]       = fmaxf(acc[mt][nt][1], 0.f);
            hid[(r0 + 8) * HIDSTR + c]     = fmaxf(acc[mt][nt][2], 0.f);
            hid[(r0 + 8) * HIDSTR + c + 1] = fmaxf(acc[mt][nt][3], 0.f);
        }
    }
    __syncthreads();

    // second gemm: out[128][16] = hid[128][128] @ W2[128][16], 2-way h split
    int r = tid & 127;
    int q = tid >> 7;  // 0..1
    float o[N_CLASS];
    #pragma unroll
    for (int c = 0; c < N_CLASS; c++) o[c] = 0.f;
    int h0 = q * 64;
    #pragma unroll 4
    for (int h = h0; h < h0 + 64; h++) {
        float v = hid[r * HIDSTR + h];
        #pragma unroll
        for (int c = 0; c < N_CLASS; c++) o[c] += v * W2s[h * N_CLASS + c];
    }
    if (q == 0) {
        #pragma unroll
        for (int c = 0; c < N_CLASS; c++) outS[r * OUTSTR + c] = o[c];
    }
    __syncthreads();
    if (q == 1) {
        int gr = blockRow + r;
        if (gr < N_NODES) {
            float vv[N_CLASS];
            #pragma unroll
            for (int c = 0; c < N_CLASS; c++) vv[c] = outS[r * OUTSTR + c] + o[c];
            #pragma unroll
            for (int j = 0; j < 4; j++) {
                float4 v4 = make_float4(vv[j*4+0], vv[j*4+1], vv[j*4+2], vv[j*4+3]);
                *(float4*)&g_local[gr * N_CLASS + j * 4] = v4;
            }
            uint4 h0v, h1v;
            h0v.x = packh(vv[0],  vv[1]);  h0v.y = packh(vv[2],  vv[3]);
            h0v.z = packh(vv[4],  vv[5]);  h0v.w = packh(vv[6],  vv[7]);
            h1v.x = packh(vv[8],  vv[9]);  h1v.y = packh(vv[10], vv[11]);
            h1v.z = packh(vv[12], vv[13]); h1v.w = packh(vv[14], vv[15]);
            *(uint4*)&g_localh[gr * N_CLASS]     = h0v;
            *(uint4*)&g_localh[gr * N_CLASS + 8] = h1v;
        }
    }
}

// ---------------- SpMM v3: 8 lanes/node, shfl-free (broadcast idx loads), MLP=8 ----------------
// lane cpair=tid&7 owns class pair (2cpair, 2cpair+1) as one half2 gather per edge.
// All 8 lanes load the SAME g_csr addresses -> hardware broadcast, no shfl.
// 8 independent gathers in flight per iteration, 4 independent FADD chains.
template<int PHASE>
__global__ void k_spmm_t(float* __restrict__ outfinal) {
    const __half2* tbl = (const __half2*)((PHASE == 0) ? g_localh : g_tmph);
    int t = blockIdx.x * blockDim.x + threadIdx.x;
    int node = t >> 3;
    if (node >= N_NODES) return;
    int cpair = threadIdx.x & 7;

    int s = g_rowptr[node], e = g_rowptr[node + 1];
    float ax0 = 0.f, ay0 = 0.f, ax1 = 0.f, ay1 = 0.f;
    int i = s;
    for (; i + 8 <= e; i += 8) {
        int j0 = __ldg(&g_csr[i + 0]);
        int j1 = __ldg(&g_csr[i + 1]);
        int j2 = __ldg(&g_csr[i + 2]);
        int j3 = __ldg(&g_csr[i + 3]);
        int j4 = __ldg(&g_csr[i + 4]);
        int j5 = __ldg(&g_csr[i + 5]);
        int j6 = __ldg(&g_csr[i + 6]);
        int j7 = __ldg(&g_csr[i + 7]);
        float2 f0 = __half22float2(__ldg(&tbl[j0 * 8 + cpair]));
        float2 f1 = __half22float2(__ldg(&tbl[j1 * 8 + cpair]));
        float2 f2 = __half22float2(__ldg(&tbl[j2 * 8 + cpair]));
        float2 f3 = __half22float2(__ldg(&tbl[j3 * 8 + cpair]));
        float2 f4 = __half22float2(__ldg(&tbl[j4 * 8 + cpair]));
        float2 f5 = __half22float2(__ldg(&tbl[j5 * 8 + cpair]));
        float2 f6 = __half22float2(__ldg(&tbl[j6 * 8 + cpair]));
        float2 f7 = __half22float2(__ldg(&tbl[j7 * 8 + cpair]));
        ax0 += f0.x + f2.x; ay0 += f0.y + f2.y;
        ax1 += f1.x + f3.x; ay1 += f1.y + f3.y;
        ax0 += f4.x + f6.x; ay0 += f4.y + f6.y;
        ax1 += f5.x + f7.x; ay1 += f5.y + f7.y;
    }
    for (; i < e; i++) {
        int j = __ldg(&g_csr[i]);
        float2 f = __half22float2(__ldg(&tbl[j * 8 + cpair]));
        ax0 += f.x; ay0 += f.y;
    }
    float ax = ax0 + ax1, ay = ay0 + ay1;

    float sc = g_scale[node];
    float2 l2v = *(const float2*)&g_local[node * N_CLASS + 2 * cpair];
    float vx = sc * ax + ALPHA * l2v.x;
    float vy = sc * ay + ALPHA * l2v.y;

    if (PHASE == 0) {
        ((__half2*)g_tmph)[node * 8 + cpair] = __floats2half2_rn(vx, vy);
    } else {
        float m = fmaxf(vx, vy);
        #pragma unroll
        for (int k = 4; k >= 1; k >>= 1) m = fmaxf(m, __shfl_xor_sync(0xffffffffu, m, k, 8));
        float ss = __expf(vx - m) + __expf(vy - m);
        #pragma unroll
        for (int k = 4; k >= 1; k >>= 1) ss += __shfl_xor_sync(0xffffffffu, ss, k, 8);
        float lg = __logf(ss);
        float2 o = make_float2(vx - m - lg, vy - m - lg);
        *(float2*)&outfinal[node * N_CLASS + 2 * cpair] = o;
    }
}

// ---------------- launch: fork CSR chain onto side stream, join before SpMM ----------------
// k_gemm stays launch #4 (profiler slot, regression sentinel).
extern "C" void kernel_launch(void* const* d_in, const int* in_sizes, int n_in,
                              void* d_out, int out_size) {
    const float* x    = (const float*)d_in[0];
    const float* W1   = (const float*)d_in[1];
    const float* W2   = (const float*)d_in[2];
    const int*   esrc = (const int*)d_in[3];
    const int*   edst = (const int*)d_in[4];
    float* out = (float*)d_out;

    static cudaStream_t s2 = nullptr;
    static cudaEvent_t evFork = nullptr, evJoin = nullptr;
    if (s2 == nullptr) {
        cudaStreamCreateWithFlags(&s2, cudaStreamNonBlocking);
        cudaEventCreateWithFlags(&evFork, cudaEventDisableTiming);
        cudaEventCreateWithFlags(&evJoin, cudaEventDisableTiming);
        cudaFuncSetAttribute(k_gemm, cudaFuncAttributeMaxDynamicSharedMemorySize, GEMM_SMEM);
    }

    cudaEventRecord(evFork, 0);
    cudaStreamWaitEvent(s2, evFork, 0);

    // launches 1-2: CSR chain start (side stream)
    k_zero_cnt<<<(N_NODES + 255) / 256, 256, 0, s2>>>();
    k_hist<<<(N_EDGES / 4 + 255) / 256, 256, 0, s2>>>(esrc);

    // launches 3-4: feature chain (main stream) — gemm is launch #4
    k_cvt_w1<<<((N_FEAT / 2) * HIDDEN + 255) / 256, 256>>>(W1);
    k_gemm<<<(N_NODES + GBM - 1) / GBM, 256, GEMM_SMEM>>>(x, W2);

    // launches 5-7: CSR chain rest (side stream)
    k_scan1<<<NCHUNK, 1024, 0, s2>>>();
    k_scan3<<<NCHUNK, 1024, 0, s2>>>();
    k_scatter<<<(N_EDGES / 4 + 255) / 256, 256, 0, s2>>>(esrc, edst);
    cudaEventRecord(evJoin, s2);

    // join, then propagation (SpMM v3: 8 threads per node)
    cudaStreamWaitEvent(0, evJoin, 0);
    k_spmm_t<0><<<(N_NODES * 8 + 255) / 256, 256>>>(nullptr);
    k_spmm_t<1><<<(N_NODES * 8 + 255) / 256, 256>>>(out);
}